// round 12
// baseline (speedup 1.0000x reference)
#include <cuda_runtime.h>
#include <math.h>

#define D_FEAT 128
#define FULL 0xffffffffu
#define MAX_NODES 100000

// Scratch: per-node L2 norms of feature rows (allocation-free __device__ global).
__device__ float g_norms[MAX_NODES];

// ---------------------------------------------------------------------------
// Kernel 1: precompute ||features[n]|| for all nodes. Warp per node.
// DRAM-streaming bound (~6-7us) — near floor.
// ---------------------------------------------------------------------------
__global__ void __launch_bounds__(256) norms_kernel(const float* __restrict__ feats,
                                                    int n_nodes) {
    int warp = (blockIdx.x * blockDim.x + threadIdx.x) >> 5;
    int lane = threadIdx.x & 31;
    if (warp >= n_nodes) return;
    const float4* row = (const float4*)(feats + (size_t)warp * D_FEAT);
    float4 v = row[lane];
    float s = v.x * v.x + v.y * v.y + v.z * v.z + v.w * v.w;
#pragma unroll
    for (int o = 16; o; o >>= 1) s += __shfl_xor_sync(FULL, s, o);
    if (lane == 0) g_norms[warp] = sqrtf(s);
}

__device__ __forceinline__ unsigned f2ord(float f) {
    unsigned u = __float_as_uint(f);
    return (u & 0x80000000u) ? ~u : (u | 0x80000000u);
}

__device__ __forceinline__ float dot4(float4 v, float4 c) {
    return v.x * c.x + v.y * c.y + v.z * c.z + v.w * c.w;
}

// ---------------------------------------------------------------------------
// Kernel 2: per-batch-node cosine top-k aggregation. Warp per batch node.
// Lane l holds float4 chunk l of center; each neighbor row is one coalesced
// warp-wide LDG.128 (512B contiguous). Groups-of-8 transpose-reduce with
// IMMEDIATE per-group distribution (no sims4 array) to minimize live regs;
// __launch_bounds__(256,7) pushes occupancy to 87.5% for latency hiding.
// ---------------------------------------------------------------------------
__global__ void __launch_bounds__(256, 7) agg_kernel(const float* __restrict__ feats,
                                                     const int* __restrict__ nodes,
                                                     const int* __restrict__ neighs,
                                                     const int* __restrict__ ns_ptr,
                                                     float* __restrict__ out,
                                                     int B, int K) {
    int warp = (blockIdx.x * blockDim.x + threadIdx.x) >> 5;
    int lane = threadIdx.x & 31;
    if (warp >= B) return;

    int ns = ns_ptr ? __ldg(ns_ptr) : 10;
    if (ns > K) ns = K;

    int node = __ldg(&nodes[warp]);
    int myneigh = (lane < K) ? __ldg(&neighs[(size_t)warp * K + lane]) : 0;
    float mynorm = g_norms[myneigh];   // lane k's neighbor norm
    float cnorm = g_norms[node];

    const float4* crow = (const float4*)(feats + (size_t)node * D_FEAT);
    float4 c = crow[lane];

    float sim;
    if (K == 32) {
        const int4* nb = (const int4*)(neighs + (size_t)warp * 32);
        bool h16 = (lane & 16) != 0;
        bool h8  = (lane & 8)  != 0;
        bool h4  = (lane & 4)  != 0;
        int gown = lane >> 3;            // which group owns this lane's neighbor
        int src  = (lane & 7) << 2;      // source lane holding dot for neighbor lane&7
        float mydot = 0.0f;
#pragma unroll
        for (int g = 0; g < 4; g++) {
            // 8 neighbor indices via 2 uniform LDG.128 (all lanes same addr)
            int4 ia = __ldg(&nb[2 * g]);
            int4 ib = __ldg(&nb[2 * g + 1]);
            float p[8];
            p[0] = dot4(((const float4*)(feats + (size_t)ia.x * D_FEAT))[lane], c);
            p[1] = dot4(((const float4*)(feats + (size_t)ia.y * D_FEAT))[lane], c);
            p[2] = dot4(((const float4*)(feats + (size_t)ia.z * D_FEAT))[lane], c);
            p[3] = dot4(((const float4*)(feats + (size_t)ia.w * D_FEAT))[lane], c);
            p[4] = dot4(((const float4*)(feats + (size_t)ib.x * D_FEAT))[lane], c);
            p[5] = dot4(((const float4*)(feats + (size_t)ib.y * D_FEAT))[lane], c);
            p[6] = dot4(((const float4*)(feats + (size_t)ib.z * D_FEAT))[lane], c);
            p[7] = dot4(((const float4*)(feats + (size_t)ib.w * D_FEAT))[lane], c);
            // stage o=16: 8 -> 4 values (4 shfl)
#pragma unroll
            for (int i = 0; i < 4; i++) {
                float send = h16 ? p[i] : p[i + 4];
                float recv = __shfl_xor_sync(FULL, send, 16);
                p[i] = (h16 ? p[i + 4] : p[i]) + recv;
            }
            // stage o=8: 4 -> 2 (2 shfl)
#pragma unroll
            for (int i = 0; i < 2; i++) {
                float send = h8 ? p[i] : p[i + 2];
                float recv = __shfl_xor_sync(FULL, send, 8);
                p[i] = (h8 ? p[i + 2] : p[i]) + recv;
            }
            // stage o=4: 2 -> 1 (1 shfl)
            {
                float send = h4 ? p[0] : p[1];
                float recv = __shfl_xor_sync(FULL, send, 4);
                p[0] = (h4 ? p[1] : p[0]) + recv;
            }
            // finish over lane bits {1,0} (2 shfl)
            p[0] += __shfl_xor_sync(FULL, p[0], 2);
            p[0] += __shfl_xor_sync(FULL, p[0], 1);
            // p[0] on lane l = dot for neighbor 8g + ((l>>2)&7).
            // Distribute to owner lanes immediately (1 shfl):
            float dg = __shfl_sync(FULL, p[0], src);
            if (gown == g) mydot = dg;
        }
        sim = mydot / (cnorm * mynorm);
    } else {
        // generic fallback: per-neighbor butterfly
        float mydot = 0.0f;
        for (int k = 0; k < K; k++) {
            int idx = __shfl_sync(FULL, myneigh, k);
            const float4* row = (const float4*)(feats + (size_t)idx * D_FEAT);
            float4 v = row[lane];
            float pp = dot4(v, c);
#pragma unroll
            for (int o = 16; o; o >>= 1) pp += __shfl_xor_sync(FULL, pp, o);
            if (lane == k) mydot = pp;
        }
        sim = mydot / (cnorm * mynorm);
    }

    // --- top-ns selection: redux.max on order key, lowest-index tie-break ---
    unsigned key = f2ord(sim);
    if (lane >= K) key = 0u;
    unsigned sel = 0u;
    for (int i = 0; i < ns; i++) {
        unsigned m = __reduce_max_sync(FULL, key);
        unsigned b = __ballot_sync(FULL, key == m);
        int kk = __ffs(b) - 1;
        sel |= 1u << kk;
        if (lane == kk) key = 0u;
    }

    // --- mean of selected rows (re-gather: rows are L1/L2-hot) + relu ---
    float4 acc = make_float4(0.f, 0.f, 0.f, 0.f);
    unsigned m2 = sel;
    while (m2) {
        int k = __ffs(m2) - 1;
        m2 &= m2 - 1;
        int idx = __shfl_sync(FULL, myneigh, k);
        const float4* row = (const float4*)(feats + (size_t)idx * D_FEAT);
        float4 v = row[lane];
        acc.x += v.x; acc.y += v.y; acc.z += v.z; acc.w += v.w;
    }
    float inv = 1.0f / (float)ns;
    float4 o;
    o.x = fmaxf(acc.x * inv, 0.0f);
    o.y = fmaxf(acc.y * inv, 0.0f);
    o.z = fmaxf(acc.z * inv, 0.0f);
    o.w = fmaxf(acc.w * inv, 0.0f);
    ((float4*)(out + (size_t)warp * D_FEAT))[lane] = o;
}

// ---------------------------------------------------------------------------
// kernel_launch: graph-capturable, allocation-free.
// ---------------------------------------------------------------------------
extern "C" void kernel_launch(void* const* d_in, const int* in_sizes, int n_in,
                              void* d_out, int out_size) {
    const float* feats = (const float*)d_in[0];
    const int* nodes = (const int*)d_in[1];
    const int* neighs = (const int*)d_in[2];
    const int* ns_ptr = (n_in > 3) ? (const int*)d_in[3] : nullptr;

    int n_nodes = in_sizes[0] / D_FEAT;
    if (n_nodes > MAX_NODES) n_nodes = MAX_NODES;
    int B = in_sizes[1];
    int K = (B > 0) ? (in_sizes[2] / B) : 0;

    int norm_blocks = (n_nodes * 32 + 255) / 256;
    norms_kernel<<<norm_blocks, 256>>>(feats, n_nodes);

    int agg_blocks = (B * 32 + 255) / 256;
    agg_kernel<<<agg_blocks, 256>>>(feats, nodes, neighs, ns_ptr,
                                    (float*)d_out, B, K);
}

// round 13
// speedup vs baseline: 1.0591x; 1.0591x over previous
#include <cuda_runtime.h>
#include <math.h>

#define D_FEAT 128
#define FULL 0xffffffffu
#define MAX_NODES 100000

// Scratch: per-node L2 norms of feature rows (allocation-free __device__ global).
__device__ float g_norms[MAX_NODES];

// ---------------------------------------------------------------------------
// Kernel 1: precompute ||features[n]|| for all nodes. Warp per node.
// DRAM-streaming bound (~6-7us) — near floor; also pre-warms L2 with the table.
// ---------------------------------------------------------------------------
__global__ void __launch_bounds__(256) norms_kernel(const float* __restrict__ feats,
                                                    int n_nodes) {
    int warp = (blockIdx.x * blockDim.x + threadIdx.x) >> 5;
    int lane = threadIdx.x & 31;
    if (warp >= n_nodes) return;
    const float4* row = (const float4*)(feats + (size_t)warp * D_FEAT);
    float4 v = row[lane];
    float s = v.x * v.x + v.y * v.y + v.z * v.z + v.w * v.w;
#pragma unroll
    for (int o = 16; o; o >>= 1) s += __shfl_xor_sync(FULL, s, o);
    if (lane == 0) g_norms[warp] = sqrtf(s);
}

__device__ __forceinline__ unsigned f2ord(float f) {
    unsigned u = __float_as_uint(f);
    return (u & 0x80000000u) ? ~u : (u | 0x80000000u);
}

__device__ __forceinline__ float dot4(float4 v, float4 c) {
    return v.x * c.x + v.y * c.y + v.z * c.z + v.w * c.w;
}

// One selection step: pick current max key (lowest lane on ties), add to mask,
// knock out the winner.
__device__ __forceinline__ void sel_step(unsigned& key, unsigned& sel, int lane) {
    unsigned m = __reduce_max_sync(FULL, key);
    unsigned b = __ballot_sync(FULL, key == m);
    int kk = __ffs(b) - 1;
    sel |= 1u << kk;
    if (lane == kk) key = 0u;
}

// ---------------------------------------------------------------------------
// Kernel 2: per-batch-node cosine top-k aggregation. Warp per batch node.
// Lane l holds float4 chunk l of center; each neighbor row is one coalesced
// warp-wide LDG.128 (512B contiguous). Groups-of-8 transpose-reduce; lane l
// PERMANENTLY owns neighbor n(l) = 8*(l&3) + ((l>>2)&7) — exactly where the
// group tree deposits its dot — so no redistribution shuffles are needed.
// ---------------------------------------------------------------------------
__global__ void __launch_bounds__(256) agg_kernel(const float* __restrict__ feats,
                                                  const int* __restrict__ nodes,
                                                  const int* __restrict__ neighs,
                                                  const int* __restrict__ ns_ptr,
                                                  float* __restrict__ out,
                                                  int B, int K) {
    int warp = (blockIdx.x * blockDim.x + threadIdx.x) >> 5;
    int lane = threadIdx.x & 31;
    if (warp >= B) return;

    int ns = ns_ptr ? __ldg(ns_ptr) : 10;
    if (ns > K) ns = K;

    int node = __ldg(&nodes[warp]);
    float cnorm = g_norms[node];

    const float4* crow = (const float4*)(feats + (size_t)node * D_FEAT);
    float4 c = crow[lane];

    float sim;
    int myneigh;
    if (K == 32) {
        // Lane l owns neighbor n(l) = 8*(l&3) + ((l>>2)&7)  (fixed bijection).
        int nl = ((lane & 3) << 3) | ((lane >> 2) & 7);
        myneigh = __ldg(&neighs[(size_t)warp * 32 + nl]);   // same 128B line
        float mynorm = g_norms[myneigh];

        const int4* nb = (const int4*)(neighs + (size_t)warp * 32);
        bool h16 = (lane & 16) != 0;
        bool h8  = (lane & 8)  != 0;
        bool h4  = (lane & 4)  != 0;
        int gown = lane & 3;               // which group deposits this lane's dot
        float mydot = 0.0f;
#pragma unroll
        for (int g = 0; g < 4; g++) {
            // 8 neighbor indices via 2 uniform LDG.128 (all lanes same addr)
            int4 ia = __ldg(&nb[2 * g]);
            int4 ib = __ldg(&nb[2 * g + 1]);
            float p[8];
            p[0] = dot4(((const float4*)(feats + (size_t)ia.x * D_FEAT))[lane], c);
            p[1] = dot4(((const float4*)(feats + (size_t)ia.y * D_FEAT))[lane], c);
            p[2] = dot4(((const float4*)(feats + (size_t)ia.z * D_FEAT))[lane], c);
            p[3] = dot4(((const float4*)(feats + (size_t)ia.w * D_FEAT))[lane], c);
            p[4] = dot4(((const float4*)(feats + (size_t)ib.x * D_FEAT))[lane], c);
            p[5] = dot4(((const float4*)(feats + (size_t)ib.y * D_FEAT))[lane], c);
            p[6] = dot4(((const float4*)(feats + (size_t)ib.z * D_FEAT))[lane], c);
            p[7] = dot4(((const float4*)(feats + (size_t)ib.w * D_FEAT))[lane], c);
            // stage o=16: 8 -> 4 values (4 shfl)
#pragma unroll
            for (int i = 0; i < 4; i++) {
                float send = h16 ? p[i] : p[i + 4];
                float recv = __shfl_xor_sync(FULL, send, 16);
                p[i] = (h16 ? p[i + 4] : p[i]) + recv;
            }
            // stage o=8: 4 -> 2 (2 shfl)
#pragma unroll
            for (int i = 0; i < 2; i++) {
                float send = h8 ? p[i] : p[i + 2];
                float recv = __shfl_xor_sync(FULL, send, 8);
                p[i] = (h8 ? p[i + 2] : p[i]) + recv;
            }
            // stage o=4: 2 -> 1 (1 shfl)
            {
                float send = h4 ? p[0] : p[1];
                float recv = __shfl_xor_sync(FULL, send, 4);
                p[0] = (h4 ? p[1] : p[0]) + recv;
            }
            // finish over lane bits {1,0} (2 shfl)
            p[0] += __shfl_xor_sync(FULL, p[0], 2);
            p[0] += __shfl_xor_sync(FULL, p[0], 1);
            // p[0] on lane l = full dot for neighbor 8g + ((l>>2)&7).
            // Lane l owns it iff (l&3) == g — keep, no redistribution shuffle.
            if (gown == g) mydot = p[0];
        }
        sim = mydot / (cnorm * mynorm);
    } else {
        // generic fallback: per-neighbor butterfly, canonical lane order
        myneigh = (lane < K) ? __ldg(&neighs[(size_t)warp * K + lane]) : 0;
        float mynorm = g_norms[myneigh];
        float mydot = 0.0f;
        for (int k = 0; k < K; k++) {
            int idx = __shfl_sync(FULL, myneigh, k);
            const float4* row = (const float4*)(feats + (size_t)idx * D_FEAT);
            float4 v = row[lane];
            float pp = dot4(v, c);
#pragma unroll
            for (int o = 16; o; o >>= 1) pp += __shfl_xor_sync(FULL, pp, o);
            if (lane == k) mydot = pp;
        }
        sim = mydot / (cnorm * mynorm);
    }

    // --- top-ns selection: redux.max on order key, lowest-lane tie-break.
    //     (Permuted lane order is tie-safe: duplicate-index ties select the
    //      same feature row either way.) ---
    unsigned key = f2ord(sim);
    if (lane >= K) key = 0u;
    unsigned sel = 0u;
    if (ns == 10) {
#pragma unroll
        for (int i = 0; i < 10; i++) sel_step(key, sel, lane);
    } else {
        for (int i = 0; i < ns; i++) sel_step(key, sel, lane);
    }

    // --- mean of selected rows (re-gather: rows are L1/L2-hot) + relu ---
    float4 acc = make_float4(0.f, 0.f, 0.f, 0.f);
    unsigned m2 = sel;
    while (m2) {
        int k = __ffs(m2) - 1;
        m2 &= m2 - 1;
        int idx = __shfl_sync(FULL, myneigh, k);
        const float4* row = (const float4*)(feats + (size_t)idx * D_FEAT);
        float4 v = row[lane];
        acc.x += v.x; acc.y += v.y; acc.z += v.z; acc.w += v.w;
    }
    float inv = 1.0f / (float)ns;
    float4 o;
    o.x = fmaxf(acc.x * inv, 0.0f);
    o.y = fmaxf(acc.y * inv, 0.0f);
    o.z = fmaxf(acc.z * inv, 0.0f);
    o.w = fmaxf(acc.w * inv, 0.0f);
    ((float4*)(out + (size_t)warp * D_FEAT))[lane] = o;
}

// ---------------------------------------------------------------------------
// kernel_launch: graph-capturable, allocation-free.
// ---------------------------------------------------------------------------
extern "C" void kernel_launch(void* const* d_in, const int* in_sizes, int n_in,
                              void* d_out, int out_size) {
    const float* feats = (const float*)d_in[0];
    const int* nodes = (const int*)d_in[1];
    const int* neighs = (const int*)d_in[2];
    const int* ns_ptr = (n_in > 3) ? (const int*)d_in[3] : nullptr;

    int n_nodes = in_sizes[0] / D_FEAT;
    if (n_nodes > MAX_NODES) n_nodes = MAX_NODES;
    int B = in_sizes[1];
    int K = (B > 0) ? (in_sizes[2] / B) : 0;

    int norm_blocks = (n_nodes * 32 + 255) / 256;
    norms_kernel<<<norm_blocks, 256>>>(feats, n_nodes);

    int agg_blocks = (B * 32 + 255) / 256;
    agg_kernel<<<agg_blocks, 256>>>(feats, nodes, neighs, ns_ptr,
                                    (float*)d_out, B, K);
}